// round 1
// baseline (speedup 1.0000x reference)
#include <cuda_runtime.h>
#include <math.h>

// Problem constants (fixed by the reference): B=4, L=5000, D=128, H=8, d=16, K=32
#define LQ   5000
#define BQ   4
#define MROWS 20000          // B*L
#define DDIM  128
#define KSEL  32

// Scratch (allocation-free rule: __device__ globals)
__device__ float g_q[MROWS * DDIM];
__device__ float g_k[MROWS * DDIM];
__device__ float g_v[MROWS * DDIM];
__device__ float g_attn[MROWS * DDIM];

// ---------------------------------------------------------------------------
// GEMM: C[m][n] = sum_k A[m][k] * W[n][k] (+ bias[n]),  K = N = 128 fixed.
// BM = BN = 64, BK = 64 (two chunks). 256 threads, 4x4 microtile per thread.
// W tile stored k-major in smem (transpose-on-store) so inner-loop b-fetch is
// a conflict-free LDS.128; A tile m-major with pad-4 so a-fetches broadcast.
// ---------------------------------------------------------------------------
__global__ __launch_bounds__(256) void gemm128(const float* __restrict__ A,
                                               const float* __restrict__ W,
                                               const float* __restrict__ bias,
                                               float* __restrict__ C,
                                               int Mrows)
{
    __shared__ float As[64][68];   // [m][k], pad 4
    __shared__ float Bs[64][68];   // [k][n], pad 4

    const int m0  = blockIdx.x * 64;
    const int n0  = blockIdx.y * 64;
    const int tid = threadIdx.x;
    const int c4  = tid & 15;      // float4 column within 64-wide chunk
    const int r0  = tid >> 4;      // 0..15
    const int tx  = tid & 15;
    const int ty  = tid >> 4;

    float acc[4][4] = {};

    for (int kt = 0; kt < 2; kt++) {
        __syncthreads();   // protect reads of previous chunk
        #pragma unroll
        for (int i = 0; i < 4; i++) {
            int rr = r0 + 16 * i;
            int m  = m0 + rr;
            float4 av = (m < Mrows)
                ? *(const float4*)&A[(size_t)m * DDIM + kt * 64 + c4 * 4]
                : make_float4(0.f, 0.f, 0.f, 0.f);
            *(float4*)&As[rr][c4 * 4] = av;

            float4 wv = *(const float4*)&W[(size_t)(n0 + rr) * DDIM + kt * 64 + c4 * 4];
            Bs[c4 * 4 + 0][rr] = wv.x;
            Bs[c4 * 4 + 1][rr] = wv.y;
            Bs[c4 * 4 + 2][rr] = wv.z;
            Bs[c4 * 4 + 3][rr] = wv.w;
        }
        __syncthreads();

        #pragma unroll 8
        for (int k = 0; k < 64; k++) {
            float a0 = As[ty * 4 + 0][k];
            float a1 = As[ty * 4 + 1][k];
            float a2 = As[ty * 4 + 2][k];
            float a3 = As[ty * 4 + 3][k];
            float4 b = *(const float4*)&Bs[k][tx * 4];
            acc[0][0] += a0 * b.x; acc[0][1] += a0 * b.y; acc[0][2] += a0 * b.z; acc[0][3] += a0 * b.w;
            acc[1][0] += a1 * b.x; acc[1][1] += a1 * b.y; acc[1][2] += a1 * b.z; acc[1][3] += a1 * b.w;
            acc[2][0] += a2 * b.x; acc[2][1] += a2 * b.y; acc[2][2] += a2 * b.z; acc[2][3] += a2 * b.w;
            acc[3][0] += a3 * b.x; acc[3][1] += a3 * b.y; acc[3][2] += a3 * b.z; acc[3][3] += a3 * b.w;
        }
    }

    float4 bv = make_float4(0.f, 0.f, 0.f, 0.f);
    if (bias) bv = *(const float4*)&bias[n0 + tx * 4];

    #pragma unroll
    for (int i = 0; i < 4; i++) {
        int m = m0 + ty * 4 + i;
        if (m < Mrows) {
            float4 o;
            o.x = acc[i][0] + bv.x;
            o.y = acc[i][1] + bv.y;
            o.z = acc[i][2] + bv.z;
            o.w = acc[i][3] + bv.w;
            *(float4*)&C[(size_t)m * DDIM + n0 + tx * 4] = o;
        }
    }
}

// ---------------------------------------------------------------------------
// Attention: one block (128 threads) per (b,l).
//  - gather 32 k-rows (stored transposed, [d][kk], pad makes both the
//    transpose store and the score reads conflict-free) and 32 v-rows
//  - scores[h][kk] = 0.25 * <q[h], k_kk[h]>   (d = 16, scale = 1/4)
//  - softmax over kk per head
//  - out[c] = sum_kk A[h(c)][kk] * v_kk[c]
// ---------------------------------------------------------------------------
__global__ __launch_bounds__(128) void attn_kernel(const int* __restrict__ kidx)
{
    __shared__ float sKT[128][33];   // [d][kk], pad 1 -> conflict-free both ways
    __shared__ float sV[32][132];    // [kk][d], pad 4
    __shared__ float sQ[128];
    __shared__ float sS[8][33];      // scores / probs
    __shared__ int   sIdx[32];

    const int bl   = blockIdx.x;          // b*L + l
    const int l    = bl % LQ;
    const int base = bl - l;              // b*L
    const int t    = threadIdx.x;
    const int warp = t >> 5;
    const int lane = t & 31;

    sQ[t] = g_q[(size_t)bl * DDIM + t];
    if (t < KSEL) sIdx[t] = kidx[l * KSEL + t];
    __syncthreads();

    // Gather K (transposed) and V rows
    for (int r = warp; r < KSEL; r += 4) {
        size_t row = (size_t)(base + sIdx[r]) * DDIM;
        float4 kv = *(const float4*)&g_k[row + lane * 4];
        sKT[lane * 4 + 0][r] = kv.x;
        sKT[lane * 4 + 1][r] = kv.y;
        sKT[lane * 4 + 2][r] = kv.z;
        sKT[lane * 4 + 3][r] = kv.w;
        float4 vv = *(const float4*)&g_v[row + lane * 4];
        *(float4*)&sV[r][lane * 4] = vv;
    }
    __syncthreads();

    // Scores: 256 entries (8 heads x 32 keys), 2 per thread
    #pragma unroll
    for (int e = t; e < 256; e += 128) {
        int h = e >> 5, kk = e & 31;
        float s = 0.f;
        #pragma unroll
        for (int dd = 0; dd < 16; dd++)
            s += sQ[h * 16 + dd] * sKT[h * 16 + dd][kk];
        sS[h][kk] = s * 0.25f;
    }
    __syncthreads();

    // Softmax per head (8 heads handled serially by threads 0..7)
    if (t < 8) {
        float mx = -1e30f;
        #pragma unroll
        for (int kk = 0; kk < KSEL; kk++) mx = fmaxf(mx, sS[t][kk]);
        float sum = 0.f;
        #pragma unroll
        for (int kk = 0; kk < KSEL; kk++) {
            float e = __expf(sS[t][kk] - mx);
            sS[t][kk] = e;
            sum += e;
        }
        float inv = 1.f / sum;
        #pragma unroll
        for (int kk = 0; kk < KSEL; kk++) sS[t][kk] *= inv;
    }
    __syncthreads();

    // Weighted sum of V
    int h = t >> 4;
    float acc = 0.f;
    #pragma unroll
    for (int kk = 0; kk < KSEL; kk++)
        acc += sS[h][kk] * sV[kk][t];
    g_attn[(size_t)bl * DDIM + t] = acc;
}

// ---------------------------------------------------------------------------
// kernel_launch: QKV GEMMs -> attention -> output GEMM (+bias)
// ---------------------------------------------------------------------------
extern "C" void kernel_launch(void* const* d_in, const int* in_sizes, int n_in,
                              void* d_out, int out_size)
{
    const float* x    = (const float*)d_in[0];
    const int*   kidx = (const int*)d_in[1];
    const float* Wq   = (const float*)d_in[2];
    const float* Wk   = (const float*)d_in[3];
    const float* Wv   = (const float*)d_in[4];
    const float* Wo   = (const float*)d_in[5];
    const float* bo   = (const float*)d_in[6];
    float* out = (float*)d_out;

    float *q, *k, *v, *attn;
    cudaGetSymbolAddress((void**)&q,    g_q);
    cudaGetSymbolAddress((void**)&k,    g_k);
    cudaGetSymbolAddress((void**)&v,    g_v);
    cudaGetSymbolAddress((void**)&attn, g_attn);

    dim3 grid((MROWS + 63) / 64, 2);
    gemm128<<<grid, 256>>>(x, Wq, nullptr, q, MROWS);
    gemm128<<<grid, 256>>>(x, Wk, nullptr, k, MROWS);
    gemm128<<<grid, 256>>>(x, Wv, nullptr, v, MROWS);

    attn_kernel<<<MROWS, 128>>>(kidx);

    gemm128<<<grid, 256>>>(attn, Wo, bo, out, MROWS);
}

// round 2
// speedup vs baseline: 1.3811x; 1.3811x over previous
#include <cuda_runtime.h>
#include <math.h>

// Problem constants (fixed by the reference): B=4, L=5000, D=128, H=8, d=16, K=32
#define LQ   5000
#define BQ   4
#define MROWS 20000          // B*L
#define DDIM  128
#define KSEL  32

// Scratch (allocation-free rule: __device__ globals)
__device__ float g_q[MROWS * DDIM];
__device__ float g_k[MROWS * DDIM];
__device__ float g_v[MROWS * DDIM];
__device__ float g_attn[MROWS * DDIM];

// ---------------------------------------------------------------------------
// GEMM: C[m][n] = sum_k A[m][k] * W[n][k] (+ bias[n]),  K = N = 128 fixed.
// BM = BN = 64, BK = 64 (two chunks). 256 threads, 4x4 microtile per thread.
// (Measured at ~89% of the fp32 FMA pipe ceiling — left unchanged this round.)
// ---------------------------------------------------------------------------
__global__ __launch_bounds__(256) void gemm128(const float* __restrict__ A,
                                               const float* __restrict__ W,
                                               const float* __restrict__ bias,
                                               float* __restrict__ C,
                                               int Mrows)
{
    __shared__ float As[64][68];   // [m][k], pad 4
    __shared__ float Bs[64][68];   // [k][n], pad 4

    const int m0  = blockIdx.x * 64;
    const int n0  = blockIdx.y * 64;
    const int tid = threadIdx.x;
    const int c4  = tid & 15;      // float4 column within 64-wide chunk
    const int r0  = tid >> 4;      // 0..15
    const int tx  = tid & 15;
    const int ty  = tid >> 4;

    float acc[4][4] = {};

    for (int kt = 0; kt < 2; kt++) {
        __syncthreads();   // protect reads of previous chunk
        #pragma unroll
        for (int i = 0; i < 4; i++) {
            int rr = r0 + 16 * i;
            int m  = m0 + rr;
            float4 av = (m < Mrows)
                ? *(const float4*)&A[(size_t)m * DDIM + kt * 64 + c4 * 4]
                : make_float4(0.f, 0.f, 0.f, 0.f);
            *(float4*)&As[rr][c4 * 4] = av;

            float4 wv = *(const float4*)&W[(size_t)(n0 + rr) * DDIM + kt * 64 + c4 * 4];
            Bs[c4 * 4 + 0][rr] = wv.x;
            Bs[c4 * 4 + 1][rr] = wv.y;
            Bs[c4 * 4 + 2][rr] = wv.z;
            Bs[c4 * 4 + 3][rr] = wv.w;
        }
        __syncthreads();

        #pragma unroll 8
        for (int k = 0; k < 64; k++) {
            float a0 = As[ty * 4 + 0][k];
            float a1 = As[ty * 4 + 1][k];
            float a2 = As[ty * 4 + 2][k];
            float a3 = As[ty * 4 + 3][k];
            float4 b = *(const float4*)&Bs[k][tx * 4];
            acc[0][0] += a0 * b.x; acc[0][1] += a0 * b.y; acc[0][2] += a0 * b.z; acc[0][3] += a0 * b.w;
            acc[1][0] += a1 * b.x; acc[1][1] += a1 * b.y; acc[1][2] += a1 * b.z; acc[1][3] += a1 * b.w;
            acc[2][0] += a2 * b.x; acc[2][1] += a2 * b.y; acc[2][2] += a2 * b.z; acc[2][3] += a2 * b.w;
            acc[3][0] += a3 * b.x; acc[3][1] += a3 * b.y; acc[3][2] += a3 * b.z; acc[3][3] += a3 * b.w;
        }
    }

    float4 bv = make_float4(0.f, 0.f, 0.f, 0.f);
    if (bias) bv = *(const float4*)&bias[n0 + tx * 4];

    #pragma unroll
    for (int i = 0; i < 4; i++) {
        int m = m0 + ty * 4 + i;
        if (m < Mrows) {
            float4 o;
            o.x = acc[i][0] + bv.x;
            o.y = acc[i][1] + bv.y;
            o.z = acc[i][2] + bv.z;
            o.w = acc[i][3] + bv.w;
            *(float4*)&C[(size_t)m * DDIM + n0 + tx * 4] = o;
        }
    }
}

// ---------------------------------------------------------------------------
// Attention v2: one block (128 threads) per (b,l). Register-resident, no smem
// K/V tiles, no transpose.
//
// Lane l of every warp owns channels [4l, 4l+4) -> head h = l>>2 (16 ch/head).
// Score pass: warp w handles keys r = w, 4+w, ..., 28+w. A coalesced float4
//   load of the k-row gives each lane its 4 channels; per-lane partial dot
//   against register q4; shfl_xor(1),shfl_xor(2) completes the 16-dim head
//   dot inside the 4-lane group. Lanes l%4==0 write 8 scores (conflict-free).
// Softmax: warp 0, lane = key index, butterfly max/sum per head.
// V pass: same row mapping; acc4 += prob * v4 in registers; one small
//   cross-warp smem reduction at the end.
// ---------------------------------------------------------------------------
__global__ __launch_bounds__(128) void attn_kernel(const int* __restrict__ kidx)
{
    __shared__ int   sIdx[KSEL];
    __shared__ float sS[8][33];      // [head][key], pad 1
    __shared__ float sAcc[4][DDIM];  // per-warp partial outputs

    const int bl   = blockIdx.x;          // b*L + l
    const int l    = bl % LQ;
    const int base = bl - l;              // b*L
    const int t    = threadIdx.x;
    const int w    = t >> 5;
    const int lane = t & 31;
    const int h    = lane >> 2;

    if (t < KSEL) sIdx[t] = kidx[l * KSEL + t];

    const float4 q4 = *(const float4*)&g_q[(size_t)bl * DDIM + lane * 4];
    __syncthreads();

    // Rows this warp is responsible for (keys w, 4+w, ..., 28+w)
    int rows[8];
    #pragma unroll
    for (int i = 0; i < 8; i++) rows[i] = base + sIdx[i * 4 + w];

    // ---- score pass ----
    #pragma unroll
    for (int i = 0; i < 8; i++) {
        const float4 k4 = *(const float4*)&g_k[(size_t)rows[i] * DDIM + lane * 4];
        float p = k4.x * q4.x + k4.y * q4.y + k4.z * q4.z + k4.w * q4.w;
        p += __shfl_xor_sync(0xffffffffu, p, 1);
        p += __shfl_xor_sync(0xffffffffu, p, 2);
        if ((lane & 3) == 0) sS[h][i * 4 + w] = p * 0.25f;   // scale = 1/sqrt(16)
    }
    __syncthreads();

    // ---- softmax (warp 0; lane = key index kk) ----
    if (w == 0) {
        #pragma unroll
        for (int hh = 0; hh < 8; hh++) {
            const float v = sS[hh][lane];
            float mx = v;
            #pragma unroll
            for (int ofs = 16; ofs; ofs >>= 1)
                mx = fmaxf(mx, __shfl_xor_sync(0xffffffffu, mx, ofs));
            const float e = __expf(v - mx);
            float sum = e;
            #pragma unroll
            for (int ofs = 16; ofs; ofs >>= 1)
                sum += __shfl_xor_sync(0xffffffffu, sum, ofs);
            sS[hh][lane] = e * __frcp_rn(sum);
        }
    }
    __syncthreads();

    // ---- V pass ----
    float4 acc = make_float4(0.f, 0.f, 0.f, 0.f);
    #pragma unroll
    for (int i = 0; i < 8; i++) {
        const float4 v4 = *(const float4*)&g_v[(size_t)rows[i] * DDIM + lane * 4];
        const float  a  = sS[h][i * 4 + w];
        acc.x += a * v4.x;
        acc.y += a * v4.y;
        acc.z += a * v4.z;
        acc.w += a * v4.w;
    }
    *(float4*)&sAcc[w][lane * 4] = acc;
    __syncthreads();

    // ---- cross-warp reduction + store ----
    const float o = sAcc[0][t] + sAcc[1][t] + sAcc[2][t] + sAcc[3][t];
    g_attn[(size_t)bl * DDIM + t] = o;
}

// ---------------------------------------------------------------------------
// kernel_launch: QKV GEMMs -> attention -> output GEMM (+bias)
// ---------------------------------------------------------------------------
extern "C" void kernel_launch(void* const* d_in, const int* in_sizes, int n_in,
                              void* d_out, int out_size)
{
    const float* x    = (const float*)d_in[0];
    const int*   kidx = (const int*)d_in[1];
    const float* Wq   = (const float*)d_in[2];
    const float* Wk   = (const float*)d_in[3];
    const float* Wv   = (const float*)d_in[4];
    const float* Wo   = (const float*)d_in[5];
    const float* bo   = (const float*)d_in[6];
    float* out = (float*)d_out;

    float *q, *k, *v, *attn;
    cudaGetSymbolAddress((void**)&q,    g_q);
    cudaGetSymbolAddress((void**)&k,    g_k);
    cudaGetSymbolAddress((void**)&v,    g_v);
    cudaGetSymbolAddress((void**)&attn, g_attn);

    dim3 grid((MROWS + 63) / 64, 2);
    gemm128<<<grid, 256>>>(x, Wq, nullptr, q, MROWS);
    gemm128<<<grid, 256>>>(x, Wk, nullptr, k, MROWS);
    gemm128<<<grid, 256>>>(x, Wv, nullptr, v, MROWS);

    attn_kernel<<<MROWS, 128>>>(kidx);

    gemm128<<<grid, 256>>>(attn, Wo, bo, out, MROWS);
}

// round 3
// speedup vs baseline: 1.9022x; 1.3773x over previous
#include <cuda_runtime.h>
#include <cuda_bf16.h>
#include <math.h>

// Problem constants: B=4, L=5000, D=128, H=8, d=16, K=32
#define LQ    5000
#define MROWS 20000          // B*L
#define DDIM  128
#define KSEL  32
#define WELEM (DDIM*DDIM)    // 16384

// Scratch (allocation-free rule: __device__ globals)
__device__ float g_q[MROWS * DDIM];
__device__ float g_k[MROWS * DDIM];
__device__ float g_v[MROWS * DDIM];
__device__ __nv_bfloat16 g_xhi[MROWS * DDIM];
__device__ __nv_bfloat16 g_xlo[MROWS * DDIM];
__device__ __nv_bfloat16 g_ahi[MROWS * DDIM];
__device__ __nv_bfloat16 g_alo[MROWS * DDIM];
__device__ __nv_bfloat16 g_whi[4 * WELEM];
__device__ __nv_bfloat16 g_wlo[4 * WELEM];

// ---------------------------------------------------------------------------
// Split fp32 -> (hi, lo) bf16 pair.  hi + lo reproduces x to ~2^-17 rel.
// ---------------------------------------------------------------------------
__device__ __forceinline__ void bf16_split(float v, __nv_bfloat16& hi, __nv_bfloat16& lo)
{
    hi = __float2bfloat16(v);
    lo = __float2bfloat16(v - __bfloat162float(hi));
}

// x conversion: 2.56M floats, float4-vectorized
__global__ __launch_bounds__(256) void convert_x(const float* __restrict__ x)
{
    int i = blockIdx.x * blockDim.x + threadIdx.x;   // group of 4 floats
    if (i >= MROWS * DDIM / 4) return;
    float4 v = ((const float4*)x)[i];
    union { __nv_bfloat16 b[4]; uint2 u; } H, L;
    bf16_split(v.x, H.b[0], L.b[0]);
    bf16_split(v.y, H.b[1], L.b[1]);
    bf16_split(v.z, H.b[2], L.b[2]);
    bf16_split(v.w, H.b[3], L.b[3]);
    *(uint2*)&g_xhi[i * 4] = H.u;
    *(uint2*)&g_xlo[i * 4] = L.u;
}

// W conversion: 4 x 16384 elements
__global__ __launch_bounds__(256) void convert_w(const float* __restrict__ wq,
                                                 const float* __restrict__ wk,
                                                 const float* __restrict__ wv,
                                                 const float* __restrict__ wo)
{
    int i = blockIdx.x * blockDim.x + threadIdx.x;
    if (i >= 4 * WELEM) return;
    const float* src[4] = { wq, wk, wv, wo };
    float v = src[i >> 14][i & (WELEM - 1)];
    __nv_bfloat16 hi, lo;
    bf16_split(v, hi, lo);
    g_whi[i] = hi;
    g_wlo[i] = lo;
}

// ---------------------------------------------------------------------------
// 3xBF16 tensor-core GEMM: C[m][n] = sum_k A[m][k]*W[n][k] (+bias), K=N=128.
// A = Ahi+Alo, W = Whi+Wlo; acc = AhWh + AhWl + AlWh (lo*lo dropped, ~2^-18).
// Block: 128 thr / 4 warps. Tile M=64, N=128, BK=32 (4 chunks).
// Warp tile m32 x n64 (warp grid 2x2). Smem row stride 40 bf16 (20 banks) ->
// all fragment LDS patterns conflict-free.
// mma.sync m16n8k16 row.col: A row-major [m][k], B col-major = W [n][k]. Both OK.
// ---------------------------------------------------------------------------
#define MMA_BF16(d, a, b)                                                   \
    asm volatile(                                                           \
        "mma.sync.aligned.m16n8k16.row.col.f32.bf16.bf16.f32 "              \
        "{%0,%1,%2,%3}, {%4,%5,%6,%7}, {%8,%9}, {%0,%1,%2,%3};"             \
        : "+f"(d[0]), "+f"(d[1]), "+f"(d[2]), "+f"(d[3])                    \
        : "r"(a[0]), "r"(a[1]), "r"(a[2]), "r"(a[3]), "r"(b[0]), "r"(b[1]))

__global__ __launch_bounds__(128) void gemm_bf16(const __nv_bfloat16* __restrict__ Ahi,
                                                 const __nv_bfloat16* __restrict__ Alo,
                                                 const __nv_bfloat16* __restrict__ Whi,
                                                 const __nv_bfloat16* __restrict__ Wlo,
                                                 const float* __restrict__ bias,
                                                 float* __restrict__ C,
                                                 int Mrows)
{
    __shared__ __nv_bfloat16 sAh[64][40], sAl[64][40];
    __shared__ __nv_bfloat16 sBh[128][40], sBl[128][40];

    const int m0   = blockIdx.x * 64;
    const int tid  = threadIdx.x;
    const int w    = tid >> 5;
    const int lane = tid & 31;
    const int wm   = (w >> 1) * 32;     // warp row base within tile
    const int wn   = (w & 1) * 64;      // warp col base
    const int fr   = lane >> 2;         // fragment row 0..7
    const int fc   = (lane & 3) * 2;    // fragment k-col (even)

    float acc[2][8][4] = {};

    for (int kt = 0; kt < 4; kt++) {
        __syncthreads();   // protect previous chunk reads

        // Load A tile: 64 rows x 32 k, hi+lo  (2048 bf16 each)
        #pragma unroll
        for (int it = 0; it < 2; it++) {
            int idx = tid + it * 128;        // 0..255
            int r   = idx >> 2;
            int kc  = (idx & 3) * 8;
            int m   = m0 + r;
            uint4 hv, lv;
            if (m < Mrows) {
                hv = *(const uint4*)&Ahi[(size_t)m * DDIM + kt * 32 + kc];
                lv = *(const uint4*)&Alo[(size_t)m * DDIM + kt * 32 + kc];
            } else {
                hv = make_uint4(0u, 0u, 0u, 0u);
                lv = hv;
            }
            *(uint2*)&sAh[r][kc]     = make_uint2(hv.x, hv.y);
            *(uint2*)&sAh[r][kc + 4] = make_uint2(hv.z, hv.w);
            *(uint2*)&sAl[r][kc]     = make_uint2(lv.x, lv.y);
            *(uint2*)&sAl[r][kc + 4] = make_uint2(lv.z, lv.w);
        }
        // Load W tile: 128 n x 32 k, hi+lo (4096 bf16 each)
        #pragma unroll
        for (int it = 0; it < 4; it++) {
            int idx = tid + it * 128;        // 0..511
            int n   = idx >> 2;
            int kc  = (idx & 3) * 8;
            uint4 hv = *(const uint4*)&Whi[(size_t)n * DDIM + kt * 32 + kc];
            uint4 lv = *(const uint4*)&Wlo[(size_t)n * DDIM + kt * 32 + kc];
            *(uint2*)&sBh[n][kc]     = make_uint2(hv.x, hv.y);
            *(uint2*)&sBh[n][kc + 4] = make_uint2(hv.z, hv.w);
            *(uint2*)&sBl[n][kc]     = make_uint2(lv.x, lv.y);
            *(uint2*)&sBl[n][kc + 4] = make_uint2(lv.z, lv.w);
        }
        __syncthreads();

        #pragma unroll
        for (int ks = 0; ks < 32; ks += 16) {
            unsigned ah[2][4], al[2][4];
            #pragma unroll
            for (int mt = 0; mt < 2; mt++) {
                int R = wm + mt * 16;
                ah[mt][0] = *(const unsigned*)&sAh[R + fr    ][ks + fc];
                ah[mt][1] = *(const unsigned*)&sAh[R + 8 + fr][ks + fc];
                ah[mt][2] = *(const unsigned*)&sAh[R + fr    ][ks + 8 + fc];
                ah[mt][3] = *(const unsigned*)&sAh[R + 8 + fr][ks + 8 + fc];
                al[mt][0] = *(const unsigned*)&sAl[R + fr    ][ks + fc];
                al[mt][1] = *(const unsigned*)&sAl[R + 8 + fr][ks + fc];
                al[mt][2] = *(const unsigned*)&sAl[R + fr    ][ks + 8 + fc];
                al[mt][3] = *(const unsigned*)&sAl[R + 8 + fr][ks + 8 + fc];
            }
            unsigned bh[8][2], bl[8][2];
            #pragma unroll
            for (int nt = 0; nt < 8; nt++) {
                int Cc = wn + nt * 8 + fr;
                bh[nt][0] = *(const unsigned*)&sBh[Cc][ks + fc];
                bh[nt][1] = *(const unsigned*)&sBh[Cc][ks + 8 + fc];
                bl[nt][0] = *(const unsigned*)&sBl[Cc][ks + fc];
                bl[nt][1] = *(const unsigned*)&sBl[Cc][ks + 8 + fc];
            }
            #pragma unroll
            for (int mt = 0; mt < 2; mt++)
                #pragma unroll
                for (int nt = 0; nt < 8; nt++) {
                    MMA_BF16(acc[mt][nt], ah[mt], bh[nt]);
                    MMA_BF16(acc[mt][nt], ah[mt], bl[nt]);
                    MMA_BF16(acc[mt][nt], al[mt], bh[nt]);
                }
        }
    }

    // Epilogue
    #pragma unroll
    for (int mt = 0; mt < 2; mt++) {
        int m = m0 + wm + mt * 16 + fr;
        #pragma unroll
        for (int nt = 0; nt < 8; nt++) {
            int n = wn + nt * 8 + fc;
            float2 bb = make_float2(0.f, 0.f);
            if (bias) bb = *(const float2*)&bias[n];
            if (m < Mrows)
                *(float2*)&C[(size_t)m * DDIM + n] =
                    make_float2(acc[mt][nt][0] + bb.x, acc[mt][nt][1] + bb.y);
            if (m + 8 < Mrows)
                *(float2*)&C[(size_t)(m + 8) * DDIM + n] =
                    make_float2(acc[mt][nt][2] + bb.x, acc[mt][nt][3] + bb.y);
        }
    }
}

// ---------------------------------------------------------------------------
// Attention (unchanged math from R2) — but emits bf16 hi/lo for the Wo GEMM.
// ---------------------------------------------------------------------------
__global__ __launch_bounds__(128) void attn_kernel(const int* __restrict__ kidx)
{
    __shared__ int   sIdx[KSEL];
    __shared__ float sS[8][33];
    __shared__ float sAcc[4][DDIM];

    const int bl   = blockIdx.x;
    const int l    = bl % LQ;
    const int base = bl - l;
    const int t    = threadIdx.x;
    const int w    = t >> 5;
    const int lane = t & 31;
    const int h    = lane >> 2;

    if (t < KSEL) sIdx[t] = kidx[l * KSEL + t];

    const float4 q4 = *(const float4*)&g_q[(size_t)bl * DDIM + lane * 4];
    __syncthreads();

    int rows[8];
    #pragma unroll
    for (int i = 0; i < 8; i++) rows[i] = base + sIdx[i * 4 + w];

    #pragma unroll
    for (int i = 0; i < 8; i++) {
        const float4 k4 = *(const float4*)&g_k[(size_t)rows[i] * DDIM + lane * 4];
        float p = k4.x * q4.x + k4.y * q4.y + k4.z * q4.z + k4.w * q4.w;
        p += __shfl_xor_sync(0xffffffffu, p, 1);
        p += __shfl_xor_sync(0xffffffffu, p, 2);
        if ((lane & 3) == 0) sS[h][i * 4 + w] = p * 0.25f;
    }
    __syncthreads();

    if (w == 0) {
        #pragma unroll
        for (int hh = 0; hh < 8; hh++) {
            const float v = sS[hh][lane];
            float mx = v;
            #pragma unroll
            for (int ofs = 16; ofs; ofs >>= 1)
                mx = fmaxf(mx, __shfl_xor_sync(0xffffffffu, mx, ofs));
            const float e = __expf(v - mx);
            float sum = e;
            #pragma unroll
            for (int ofs = 16; ofs; ofs >>= 1)
                sum += __shfl_xor_sync(0xffffffffu, sum, ofs);
            sS[hh][lane] = e * __frcp_rn(sum);
        }
    }
    __syncthreads();

    float4 acc = make_float4(0.f, 0.f, 0.f, 0.f);
    #pragma unroll
    for (int i = 0; i < 8; i++) {
        const float4 v4 = *(const float4*)&g_v[(size_t)rows[i] * DDIM + lane * 4];
        const float  a  = sS[h][i * 4 + w];
        acc.x += a * v4.x;
        acc.y += a * v4.y;
        acc.z += a * v4.z;
        acc.w += a * v4.w;
    }
    *(float4*)&sAcc[w][lane * 4] = acc;
    __syncthreads();

    const float o = sAcc[0][t] + sAcc[1][t] + sAcc[2][t] + sAcc[3][t];
    __nv_bfloat16 hi, lo;
    bf16_split(o, hi, lo);
    g_ahi[(size_t)bl * DDIM + t] = hi;
    g_alo[(size_t)bl * DDIM + t] = lo;
}

// ---------------------------------------------------------------------------
extern "C" void kernel_launch(void* const* d_in, const int* in_sizes, int n_in,
                              void* d_out, int out_size)
{
    const float* x    = (const float*)d_in[0];
    const int*   kidx = (const int*)d_in[1];
    const float* Wq   = (const float*)d_in[2];
    const float* Wk   = (const float*)d_in[3];
    const float* Wv   = (const float*)d_in[4];
    const float* Wo   = (const float*)d_in[5];
    const float* bo   = (const float*)d_in[6];
    float* out = (float*)d_out;

    float *q, *k, *v;
    __nv_bfloat16 *xhi, *xlo, *ahi, *alo, *whi, *wlo;
    cudaGetSymbolAddress((void**)&q,   g_q);
    cudaGetSymbolAddress((void**)&k,   g_k);
    cudaGetSymbolAddress((void**)&v,   g_v);
    cudaGetSymbolAddress((void**)&xhi, g_xhi);
    cudaGetSymbolAddress((void**)&xlo, g_xlo);
    cudaGetSymbolAddress((void**)&ahi, g_ahi);
    cudaGetSymbolAddress((void**)&alo, g_alo);
    cudaGetSymbolAddress((void**)&whi, g_whi);
    cudaGetSymbolAddress((void**)&wlo, g_wlo);

    convert_x<<<(MROWS * DDIM / 4 + 255) / 256, 256>>>(x);
    convert_w<<<(4 * WELEM + 255) / 256, 256>>>(Wq, Wk, Wv, Wo);

    const int gblocks = (MROWS + 63) / 64;   // 313
    gemm_bf16<<<gblocks, 128>>>(xhi, xlo, whi,             wlo,             nullptr, q, MROWS);
    gemm_bf16<<<gblocks, 128>>>(xhi, xlo, whi + WELEM,     wlo + WELEM,     nullptr, k, MROWS);
    gemm_bf16<<<gblocks, 128>>>(xhi, xlo, whi + 2 * WELEM, wlo + 2 * WELEM, nullptr, v, MROWS);

    attn_kernel<<<MROWS, 128>>>(kidx);

    gemm_bf16<<<gblocks, 128>>>(ahi, alo, whi + 3 * WELEM, wlo + 3 * WELEM, bo, out, MROWS);
}

// round 6
// speedup vs baseline: 2.3199x; 1.2196x over previous
#include <cuda_runtime.h>
#include <cuda_bf16.h>
#include <math.h>

// Problem constants: B=4, L=5000, D=128, H=8, d=16, K=32
#define LQ    5000
#define MROWS 20000          // B*L
#define DDIM  128
#define KSEL  32
#define WELEM (DDIM*DDIM)    // 16384

// Scratch (allocation-free rule: __device__ globals)
__device__ float g_q[MROWS * DDIM];
__device__ float g_k[MROWS * DDIM];
__device__ float g_v[MROWS * DDIM];
__device__ float g_attn[MROWS * DDIM];
__device__ __nv_bfloat16 g_whi[4 * WELEM];
__device__ __nv_bfloat16 g_wlo[4 * WELEM];

// ---------------------------------------------------------------------------
__device__ __forceinline__ void bf16_split(float v, __nv_bfloat16& hi, __nv_bfloat16& lo)
{
    hi = __float2bfloat16(v);
    lo = __float2bfloat16(v - __bfloat162float(hi));
}

// W conversion: 4 x 16384 elements (tiny)
__global__ __launch_bounds__(256) void convert_w(const float* __restrict__ wq,
                                                 const float* __restrict__ wk,
                                                 const float* __restrict__ wv,
                                                 const float* __restrict__ wo)
{
    int i = blockIdx.x * blockDim.x + threadIdx.x;
    if (i >= 4 * WELEM) return;
    const float* src[4] = { wq, wk, wv, wo };
    float v = src[i >> 14][i & (WELEM - 1)];
    __nv_bfloat16 hi, lo;
    bf16_split(v, hi, lo);
    g_whi[i] = hi;
    g_wlo[i] = lo;
}

// ---------------------------------------------------------------------------
// 3xBF16 tensor GEMM v2: C[m][n] = sum_k A[m][k]*W[n][k] (+bias), K=N=128.
// A read as FP32 and split to (hi,lo) bf16 in-kernel at STS time.
// 256 threads / 8 warps; tile M=128 x N=128; BK=32 (4 chunks), double-buffered
// DYNAMIC smem (80 KB) with register-staged global prefetch. ldmatrix.x4.
// Warp tile m32 x n64 (warp grid 4x2). Smem row stride 40 bf16 (80 B):
// 8-row ldmatrix phases hit 8 distinct 16B slots mod 128 B -> conflict-free.
// blockIdx.y selects weight matrix / output (QKV fusion).
// ---------------------------------------------------------------------------
#define MMA_BF16(d, a, b)                                                   \
    asm volatile(                                                           \
        "mma.sync.aligned.m16n8k16.row.col.f32.bf16.bf16.f32 "              \
        "{%0,%1,%2,%3}, {%4,%5,%6,%7}, {%8,%9}, {%0,%1,%2,%3};"             \
        : "+f"(d[0]), "+f"(d[1]), "+f"(d[2]), "+f"(d[3])                    \
        : "r"(a[0]), "r"(a[1]), "r"(a[2]), "r"(a[3]), "r"(b[0]), "r"(b[1]))

__device__ __forceinline__ void ldsm4(unsigned* r, unsigned addr)
{
    asm volatile("ldmatrix.sync.aligned.m8n8.x4.shared.b16 {%0,%1,%2,%3}, [%4];"
                 : "=r"(r[0]), "=r"(r[1]), "=r"(r[2]), "=r"(r[3]) : "r"(addr));
}

#define SROW 40                          // bf16 row stride (80 B)
#define PLANE (128 * SROW)               // elements per matrix plane
#define ABYTES (PLANE * 2)               // 10240 B per plane
#define BUFELEM (4 * PLANE)              // elements per buffer (4 planes)
#define GSMEM_BYTES (2 * BUFELEM * 2)    // 81920 B total

__global__ __launch_bounds__(256, 2) void gemm_bf16(const float* __restrict__ A,
                                                    const __nv_bfloat16* __restrict__ WhiB,
                                                    const __nv_bfloat16* __restrict__ WloB,
                                                    const float* __restrict__ bias,
                                                    float* __restrict__ C0,
                                                    float* __restrict__ C1,
                                                    float* __restrict__ C2)
{
    extern __shared__ __nv_bfloat16 smem[];   // [2][4 * 128 * SROW]

    const int y    = blockIdx.y;
    const __nv_bfloat16* Wh = WhiB + y * WELEM;
    const __nv_bfloat16* Wl = WloB + y * WELEM;
    float* C = (y == 0) ? C0 : (y == 1) ? C1 : C2;

    const int m0   = blockIdx.x * 128;
    const int tid  = threadIdx.x;
    const int w    = tid >> 5;
    const int lane = tid & 31;
    const int wm   = (w >> 1) * 32;     // warp row base (4 warps in m)
    const int wn   = (w & 1) * 64;      // warp col base (2 warps in n)
    const int fr   = lane >> 2;
    const int fc   = (lane & 3) * 2;

    // per-lane ldmatrix byte offsets (within a 128x40 plane)
    const unsigned laneA = (unsigned)((wm + (lane & 15)) * (SROW * 2) + ((lane >> 4) & 1) * 16);
    const unsigned laneB = (unsigned)((wn + ((lane >> 4) & 1) * 8 + (lane & 7)) * (SROW * 2)
                                      + ((lane >> 3) & 1) * 16);
    unsigned sb[2];
    sb[0] = (unsigned)__cvta_generic_to_shared(&smem[0]);
    sb[1] = (unsigned)__cvta_generic_to_shared(&smem[BUFELEM]);

    // staging: thread owns row r = tid>>1, half hf = tid&1 (16 elements)
    const int r  = tid >> 1;
    const int hf = tid & 1;
    const int m  = m0 + r;
    const bool mok = (m < MROWS);

    float4 aR[4];
    uint4  whR[2], wlR[2];

    auto stage = [&](int kt) {
        const int kc = kt * 32 + hf * 16;
        if (mok) {
            const float4* s = (const float4*)&A[(size_t)m * DDIM + kc];
            aR[0] = s[0]; aR[1] = s[1]; aR[2] = s[2]; aR[3] = s[3];
        } else {
            aR[0] = aR[1] = aR[2] = aR[3] = make_float4(0.f, 0.f, 0.f, 0.f);
        }
        const uint4* wh = (const uint4*)&Wh[(size_t)r * DDIM + kc];
        const uint4* wl = (const uint4*)&Wl[(size_t)r * DDIM + kc];
        whR[0] = wh[0]; whR[1] = wh[1];
        wlR[0] = wl[0]; wlR[1] = wl[1];
    };

    auto commit = [&](int b) {
        __nv_bfloat16* Ah = &smem[b * BUFELEM];
        __nv_bfloat16* Al = Ah + PLANE;
        __nv_bfloat16* Bh = Al + PLANE;
        __nv_bfloat16* Bl = Bh + PLANE;
        union { __nv_bfloat16 h[16]; uint4 u[2]; } H, L;
        const float* af = (const float*)aR;
        #pragma unroll
        for (int i = 0; i < 16; i++) bf16_split(af[i], H.h[i], L.h[i]);
        uint4* dAh = (uint4*)&Ah[r * SROW + hf * 16];
        uint4* dAl = (uint4*)&Al[r * SROW + hf * 16];
        dAh[0] = H.u[0]; dAh[1] = H.u[1];
        dAl[0] = L.u[0]; dAl[1] = L.u[1];
        uint4* dBh = (uint4*)&Bh[r * SROW + hf * 16];
        uint4* dBl = (uint4*)&Bl[r * SROW + hf * 16];
        dBh[0] = whR[0]; dBh[1] = whR[1];
        dBl[0] = wlR[0]; dBl[1] = wlR[1];
    };

    float acc[2][8][4] = {};

    stage(0);
    commit(0);
    __syncthreads();

    for (int kt = 0; kt < 4; kt++) {
        if (kt < 3) stage(kt + 1);

        const unsigned base = sb[kt & 1];
        const unsigned offAh = 0, offAl = ABYTES, offBh = 2 * ABYTES, offBl = 3 * ABYTES;

        #pragma unroll
        for (int ks = 0; ks < 32; ks += 16) {
            unsigned ah[2][4], al[2][4];
            #pragma unroll
            for (int mt = 0; mt < 2; mt++) {
                ldsm4(ah[mt], base + offAh + laneA + (unsigned)(mt * 16 * SROW * 2 + ks * 2));
                ldsm4(al[mt], base + offAl + laneA + (unsigned)(mt * 16 * SROW * 2 + ks * 2));
            }
            #pragma unroll
            for (int ntp = 0; ntp < 4; ntp++) {
                unsigned bh[4], bl[4];
                ldsm4(bh, base + offBh + laneB + (unsigned)(ntp * 16 * SROW * 2 + ks * 2));
                ldsm4(bl, base + offBl + laneB + (unsigned)(ntp * 16 * SROW * 2 + ks * 2));
                #pragma unroll
                for (int mt = 0; mt < 2; mt++) {
                    MMA_BF16(acc[mt][ntp * 2],     ah[mt], (bh + 0));
                    MMA_BF16(acc[mt][ntp * 2],     ah[mt], (bl + 0));
                    MMA_BF16(acc[mt][ntp * 2],     al[mt], (bh + 0));
                    MMA_BF16(acc[mt][ntp * 2 + 1], ah[mt], (bh + 2));
                    MMA_BF16(acc[mt][ntp * 2 + 1], ah[mt], (bl + 2));
                    MMA_BF16(acc[mt][ntp * 2 + 1], al[mt], (bh + 2));
                }
            }
        }

        if (kt < 3) {
            commit((kt + 1) & 1);
            __syncthreads();
        }
    }

    // Epilogue
    #pragma unroll
    for (int mt = 0; mt < 2; mt++) {
        int mrow = m0 + wm + mt * 16 + fr;
        #pragma unroll
        for (int nt = 0; nt < 8; nt++) {
            int n = wn + nt * 8 + fc;
            float2 bb = make_float2(0.f, 0.f);
            if (bias) bb = *(const float2*)&bias[n];
            if (mrow < MROWS)
                *(float2*)&C[(size_t)mrow * DDIM + n] =
                    make_float2(acc[mt][nt][0] + bb.x, acc[mt][nt][1] + bb.y);
            if (mrow + 8 < MROWS)
                *(float2*)&C[(size_t)(mrow + 8) * DDIM + n] =
                    make_float2(acc[mt][nt][2] + bb.x, acc[mt][nt][3] + bb.y);
        }
    }
}

// ---------------------------------------------------------------------------
// Attention: register-resident gather attention, softmax distributed across
// all 4 warps; writes fp32 g_attn.
// ---------------------------------------------------------------------------
__global__ __launch_bounds__(128) void attn_kernel(const int* __restrict__ kidx)
{
    __shared__ int   sIdx[KSEL];
    __shared__ float sS[8][33];
    __shared__ float sAcc[4][DDIM];

    const int bl   = blockIdx.x;
    const int l    = bl % LQ;
    const int base = bl - l;
    const int t    = threadIdx.x;
    const int w    = t >> 5;
    const int lane = t & 31;
    const int h    = lane >> 2;

    if (t < KSEL) sIdx[t] = kidx[l * KSEL + t];

    const float4 q4 = *(const float4*)&g_q[(size_t)bl * DDIM + lane * 4];
    __syncthreads();

    int rows[8];
    #pragma unroll
    for (int i = 0; i < 8; i++) rows[i] = base + sIdx[i * 4 + w];

    #pragma unroll
    for (int i = 0; i < 8; i++) {
        const float4 k4 = *(const float4*)&g_k[(size_t)rows[i] * DDIM + lane * 4];
        float p = k4.x * q4.x + k4.y * q4.y + k4.z * q4.z + k4.w * q4.w;
        p += __shfl_xor_sync(0xffffffffu, p, 1);
        p += __shfl_xor_sync(0xffffffffu, p, 2);
        if ((lane & 3) == 0) sS[h][i * 4 + w] = p * 0.25f;
    }
    __syncthreads();

    // softmax: warp w handles heads 2w, 2w+1 (lane = key index)
    #pragma unroll
    for (int j = 0; j < 2; j++) {
        const int hh = w * 2 + j;
        const float v = sS[hh][lane];
        float mx = v;
        #pragma unroll
        for (int ofs = 16; ofs; ofs >>= 1)
            mx = fmaxf(mx, __shfl_xor_sync(0xffffffffu, mx, ofs));
        const float e = __expf(v - mx);
        float sum = e;
        #pragma unroll
        for (int ofs = 16; ofs; ofs >>= 1)
            sum += __shfl_xor_sync(0xffffffffu, sum, ofs);
        sS[hh][lane] = e * __frcp_rn(sum);
    }
    __syncthreads();

    float4 acc = make_float4(0.f, 0.f, 0.f, 0.f);
    #pragma unroll
    for (int i = 0; i < 8; i++) {
        const float4 v4 = *(const float4*)&g_v[(size_t)rows[i] * DDIM + lane * 4];
        const float  a  = sS[h][i * 4 + w];
        acc.x += a * v4.x;
        acc.y += a * v4.y;
        acc.z += a * v4.z;
        acc.w += a * v4.w;
    }
    *(float4*)&sAcc[w][lane * 4] = acc;
    __syncthreads();

    g_attn[(size_t)bl * DDIM + t] = sAcc[0][t] + sAcc[1][t] + sAcc[2][t] + sAcc[3][t];
}

// ---------------------------------------------------------------------------
extern "C" void kernel_launch(void* const* d_in, const int* in_sizes, int n_in,
                              void* d_out, int out_size)
{
    const float* x    = (const float*)d_in[0];
    const int*   kidx = (const int*)d_in[1];
    const float* Wq   = (const float*)d_in[2];
    const float* Wk   = (const float*)d_in[3];
    const float* Wv   = (const float*)d_in[4];
    const float* Wo   = (const float*)d_in[5];
    const float* bo   = (const float*)d_in[6];
    float* out = (float*)d_out;

    float *q, *k, *v, *attn;
    __nv_bfloat16 *whi, *wlo;
    cudaGetSymbolAddress((void**)&q,    g_q);
    cudaGetSymbolAddress((void**)&k,    g_k);
    cudaGetSymbolAddress((void**)&v,    g_v);
    cudaGetSymbolAddress((void**)&attn, g_attn);
    cudaGetSymbolAddress((void**)&whi,  g_whi);
    cudaGetSymbolAddress((void**)&wlo,  g_wlo);

    // Raise dynamic smem cap for the GEMM. Idempotent, not a stream op,
    // called unconditionally every invocation (no static guards allowed).
    cudaFuncSetAttribute(gemm_bf16,
                         cudaFuncAttributeMaxDynamicSharedMemorySize,
                         GSMEM_BYTES);

    convert_w<<<(4 * WELEM + 255) / 256, 256>>>(Wq, Wk, Wv, Wo);

    const int mb = (MROWS + 127) / 128;   // 157
    gemm_bf16<<<dim3(mb, 3), 256, GSMEM_BYTES>>>(x, whi, wlo, nullptr, q, k, v);

    attn_kernel<<<MROWS, 128>>>(kidx);

    gemm_bf16<<<dim3(mb, 1), 256, GSMEM_BYTES>>>(attn, whi + 3 * WELEM,
                                                 wlo + 3 * WELEM, bo,
                                                 out, nullptr, nullptr);
}

// round 7
// speedup vs baseline: 2.4688x; 1.0642x over previous
#include <cuda_runtime.h>
#include <cuda_bf16.h>
#include <cuda_fp16.h>
#include <math.h>

// Problem constants: B=4, L=5000, D=128, H=8, d=16, K=32
#define LQ    5000
#define MROWS 20000          // B*L
#define DDIM  128
#define KSEL  32
#define WELEM (DDIM*DDIM)    // 16384

// Scratch (allocation-free rule: __device__ globals)
__device__ float  g_q[MROWS * DDIM];
__device__ __half g_kh[MROWS * DDIM];
__device__ __half g_vh[MROWS * DDIM];
__device__ float  g_attn[MROWS * DDIM];
__device__ __nv_bfloat16 g_whi[4 * WELEM];
__device__ __nv_bfloat16 g_wlo[4 * WELEM];

// ---------------------------------------------------------------------------
__device__ __forceinline__ void bf16_split(float v, __nv_bfloat16& hi, __nv_bfloat16& lo)
{
    hi = __float2bfloat16(v);
    lo = __float2bfloat16(v - __bfloat162float(hi));
}

// W conversion: 4 x 16384 elements (tiny)
__global__ __launch_bounds__(256) void convert_w(const float* __restrict__ wq,
                                                 const float* __restrict__ wk,
                                                 const float* __restrict__ wv,
                                                 const float* __restrict__ wo)
{
    int i = blockIdx.x * blockDim.x + threadIdx.x;
    if (i >= 4 * WELEM) return;
    const float* src[4] = { wq, wk, wv, wo };
    float v = src[i >> 14][i & (WELEM - 1)];
    __nv_bfloat16 hi, lo;
    bf16_split(v, hi, lo);
    g_whi[i] = hi;
    g_wlo[i] = lo;
}

// ---------------------------------------------------------------------------
// 3xBF16 tensor GEMM v3: C[m][n] = sum_k A[m][k]*W[n][k] (+bias), K=N=128.
// Tile M=64 x N=128, BK=32 (4 chunks), double-buffered dynamic smem (60 KB),
// register-staged prefetch, ldmatrix.x4, 256 thr / 8 warps (warp tile m16xn64,
// warp grid 4m x 2n), 3 blocks/SM target. Output fp32 (+bias) or fp16 per y.
// Smem row stride 40 bf16 (80 B): ldmatrix 8-row phases conflict-free.
// ---------------------------------------------------------------------------
#define MMA_BF16(d, a, b)                                                   \
    asm volatile(                                                           \
        "mma.sync.aligned.m16n8k16.row.col.f32.bf16.bf16.f32 "              \
        "{%0,%1,%2,%3}, {%4,%5,%6,%7}, {%8,%9}, {%0,%1,%2,%3};"             \
        : "+f"(d[0]), "+f"(d[1]), "+f"(d[2]), "+f"(d[3])                    \
        : "r"(a[0]), "r"(a[1]), "r"(a[2]), "r"(a[3]), "r"(b[0]), "r"(b[1]))

__device__ __forceinline__ void ldsm4(unsigned* r, unsigned addr)
{
    asm volatile("ldmatrix.sync.aligned.m8n8.x4.shared.b16 {%0,%1,%2,%3}, [%4];"
                 : "=r"(r[0]), "=r"(r[1]), "=r"(r[2]), "=r"(r[3]) : "r"(addr));
}

#define SROW    40                        // bf16 row stride (80 B)
#define APLANE  (64 * SROW)               // A plane elements (64 rows)
#define BPLANE  (128 * SROW)              // B plane elements (128 rows)
#define BUFELEM (2 * APLANE + 2 * BPLANE) // 15360 elements per buffer
#define BUFBYTES (BUFELEM * 2)            // 30720 B
#define OFF_AL  (APLANE * 2)              // byte offsets within buffer
#define OFF_BH  (2 * APLANE * 2)
#define OFF_BL  ((2 * APLANE + BPLANE) * 2)
#define GSMEM_BYTES (2 * BUFBYTES)        // 61440 B

__global__ __launch_bounds__(256, 3) void gemm_bf16(const float* __restrict__ A,
                                                    const __nv_bfloat16* __restrict__ WhiB,
                                                    const __nv_bfloat16* __restrict__ WloB,
                                                    const float* __restrict__ bias,
                                                    float* __restrict__ Cq,
                                                    __half* __restrict__ Ck,
                                                    __half* __restrict__ Cv)
{
    extern __shared__ __nv_bfloat16 smem[];

    const int y = blockIdx.y;
    const __nv_bfloat16* Wh = WhiB + y * WELEM;
    const __nv_bfloat16* Wl = WloB + y * WELEM;

    const int m0   = blockIdx.x * 64;
    const int tid  = threadIdx.x;
    const int w    = tid >> 5;
    const int lane = tid & 31;
    const int wm   = (w >> 1) * 16;     // 4 warps in m (m16 each)
    const int wn   = (w & 1) * 64;      // 2 warps in n (n64 each)
    const int fr   = lane >> 2;
    const int fc   = (lane & 3) * 2;

    const unsigned laneA = (unsigned)((wm + (lane & 15)) * (SROW * 2) + ((lane >> 4) & 1) * 16);
    const unsigned laneB = (unsigned)((wn + ((lane >> 4) & 1) * 8 + (lane & 7)) * (SROW * 2)
                                      + ((lane >> 3) & 1) * 16);
    unsigned sb[2];
    sb[0] = (unsigned)__cvta_generic_to_shared(&smem[0]);
    sb[1] = sb[0] + BUFBYTES;

    // A staging: thread owns row ar (4 thr/row), 8 floats at seg as*8
    const int ar = tid >> 2;            // 0..63
    const int as = tid & 3;
    const int am = m0 + ar;
    const bool mok = (am < MROWS);
    // W staging: thread owns row wr (2 thr/row), 16 halves at whf*16
    const int wr  = tid >> 1;           // 0..127
    const int whf = tid & 1;

    float4 aR[2];
    uint4  whR[2], wlR[2];

    auto stage = [&](int kt) {
        const int akc = kt * 32 + as * 8;
        if (mok) {
            const float4* s = (const float4*)&A[(size_t)am * DDIM + akc];
            aR[0] = s[0]; aR[1] = s[1];
        } else {
            aR[0] = aR[1] = make_float4(0.f, 0.f, 0.f, 0.f);
        }
        const int wkc = kt * 32 + whf * 16;
        const uint4* wh = (const uint4*)&Wh[(size_t)wr * DDIM + wkc];
        const uint4* wl = (const uint4*)&Wl[(size_t)wr * DDIM + wkc];
        whR[0] = wh[0]; whR[1] = wh[1];
        wlR[0] = wl[0]; wlR[1] = wl[1];
    };

    auto commit = [&](int b) {
        __nv_bfloat16* base = &smem[b * BUFELEM];
        union { __nv_bfloat16 h[8]; uint4 u; } H, L;
        const float* af = (const float*)aR;
        #pragma unroll
        for (int i = 0; i < 8; i++) bf16_split(af[i], H.h[i], L.h[i]);
        *(uint4*)&base[ar * SROW + as * 8]              = H.u;
        *(uint4*)&base[APLANE + ar * SROW + as * 8]     = L.u;
        *(uint4*)&base[2 * APLANE + wr * SROW + whf * 16]          = whR[0];
        *(uint4*)&base[2 * APLANE + wr * SROW + whf * 16 + 8]      = whR[1];
        *(uint4*)&base[2 * APLANE + BPLANE + wr * SROW + whf * 16]     = wlR[0];
        *(uint4*)&base[2 * APLANE + BPLANE + wr * SROW + whf * 16 + 8] = wlR[1];
    };

    float acc[8][4] = {};

    stage(0);
    commit(0);
    __syncthreads();

    for (int kt = 0; kt < 4; kt++) {
        if (kt < 3) stage(kt + 1);

        const unsigned base = sb[kt & 1];

        #pragma unroll
        for (int ks = 0; ks < 32; ks += 16) {
            unsigned ah[4], al[4];
            ldsm4(ah, base + laneA + (unsigned)(ks * 2));
            ldsm4(al, base + OFF_AL + laneA + (unsigned)(ks * 2));
            #pragma unroll
            for (int ntp = 0; ntp < 4; ntp++) {
                unsigned bh[4], bl[4];
                ldsm4(bh, base + OFF_BH + laneB + (unsigned)(ntp * 16 * SROW * 2 + ks * 2));
                ldsm4(bl, base + OFF_BL + laneB + (unsigned)(ntp * 16 * SROW * 2 + ks * 2));
                MMA_BF16(acc[ntp * 2],     ah, (bh + 0));
                MMA_BF16(acc[ntp * 2],     ah, (bl + 0));
                MMA_BF16(acc[ntp * 2],     al, (bh + 0));
                MMA_BF16(acc[ntp * 2 + 1], ah, (bh + 2));
                MMA_BF16(acc[ntp * 2 + 1], ah, (bl + 2));
                MMA_BF16(acc[ntp * 2 + 1], al, (bh + 2));
            }
        }

        if (kt < 3) {
            commit((kt + 1) & 1);
            __syncthreads();
        }
    }

    // Epilogue: y==0 -> fp32 Cq (+bias), y==1 -> fp16 Ck, y==2 -> fp16 Cv
    const int mrow = m0 + wm + fr;
    if (y == 0) {
        #pragma unroll
        for (int nt = 0; nt < 8; nt++) {
            const int n = wn + nt * 8 + fc;
            float2 bb = make_float2(0.f, 0.f);
            if (bias) bb = *(const float2*)&bias[n];
            if (mrow < MROWS)
                *(float2*)&Cq[(size_t)mrow * DDIM + n] =
                    make_float2(acc[nt][0] + bb.x, acc[nt][1] + bb.y);
            if (mrow + 8 < MROWS)
                *(float2*)&Cq[(size_t)(mrow + 8) * DDIM + n] =
                    make_float2(acc[nt][2] + bb.x, acc[nt][3] + bb.y);
        }
    } else {
        __half* H = (y == 1) ? Ck : Cv;
        #pragma unroll
        for (int nt = 0; nt < 8; nt++) {
            const int n = wn + nt * 8 + fc;
            if (mrow < MROWS)
                *(__half2*)&H[(size_t)mrow * DDIM + n] =
                    __floats2half2_rn(acc[nt][0], acc[nt][1]);
            if (mrow + 8 < MROWS)
                *(__half2*)&H[(size_t)(mrow + 8) * DDIM + n] =
                    __floats2half2_rn(acc[nt][2], acc[nt][3]);
        }
    }
}

// ---------------------------------------------------------------------------
// Attention: register-resident gather, fp16 K/V (halved gather traffic),
// fp32 Q and fp32 math; writes fp32 g_attn.
// ---------------------------------------------------------------------------
__global__ __launch_bounds__(128) void attn_kernel(const int* __restrict__ kidx)
{
    __shared__ int   sIdx[KSEL];
    __shared__ float sS[8][33];
    __shared__ float sAcc[4][DDIM];

    const int bl   = blockIdx.x;
    const int l    = bl % LQ;
    const int base = bl - l;
    const int t    = threadIdx.x;
    const int w    = t >> 5;
    const int lane = t & 31;
    const int h    = lane >> 2;

    if (t < KSEL) sIdx[t] = kidx[l * KSEL + t];

    const float4 q4 = *(const float4*)&g_q[(size_t)bl * DDIM + lane * 4];
    __syncthreads();

    int rows[8];
    #pragma unroll
    for (int i = 0; i < 8; i++) rows[i] = base + sIdx[i * 4 + w];

    #pragma unroll
    for (int i = 0; i < 8; i++) {
        const uint2 kv = *(const uint2*)&g_kh[(size_t)rows[i] * DDIM + lane * 4];
        const float2 f0 = __half22float2(*(const __half2*)&kv.x);
        const float2 f1 = __half22float2(*(const __half2*)&kv.y);
        float p = f0.x * q4.x + f0.y * q4.y + f1.x * q4.z + f1.y * q4.w;
        p += __shfl_xor_sync(0xffffffffu, p, 1);
        p += __shfl_xor_sync(0xffffffffu, p, 2);
        if ((lane & 3) == 0) sS[h][i * 4 + w] = p * 0.25f;
    }
    __syncthreads();

    // softmax: warp w handles heads 2w, 2w+1 (lane = key index)
    #pragma unroll
    for (int j = 0; j < 2; j++) {
        const int hh = w * 2 + j;
        const float v = sS[hh][lane];
        float mx = v;
        #pragma unroll
        for (int ofs = 16; ofs; ofs >>= 1)
            mx = fmaxf(mx, __shfl_xor_sync(0xffffffffu, mx, ofs));
        const float e = __expf(v - mx);
        float sum = e;
        #pragma unroll
        for (int ofs = 16; ofs; ofs >>= 1)
            sum += __shfl_xor_sync(0xffffffffu, sum, ofs);
        sS[hh][lane] = e * __frcp_rn(sum);
    }
    __syncthreads();

    float4 acc = make_float4(0.f, 0.f, 0.f, 0.f);
    #pragma unroll
    for (int i = 0; i < 8; i++) {
        const uint2 vv = *(const uint2*)&g_vh[(size_t)rows[i] * DDIM + lane * 4];
        const float2 f0 = __half22float2(*(const __half2*)&vv.x);
        const float2 f1 = __half22float2(*(const __half2*)&vv.y);
        const float a = sS[h][i * 4 + w];
        acc.x += a * f0.x;
        acc.y += a * f0.y;
        acc.z += a * f1.x;
        acc.w += a * f1.y;
    }
    *(float4*)&sAcc[w][lane * 4] = acc;
    __syncthreads();

    g_attn[(size_t)bl * DDIM + t] = sAcc[0][t] + sAcc[1][t] + sAcc[2][t] + sAcc[3][t];
}

// ---------------------------------------------------------------------------
extern "C" void kernel_launch(void* const* d_in, const int* in_sizes, int n_in,
                              void* d_out, int out_size)
{
    const float* x    = (const float*)d_in[0];
    const int*   kidx = (const int*)d_in[1];
    const float* Wq   = (const float*)d_in[2];
    const float* Wk   = (const float*)d_in[3];
    const float* Wv   = (const float*)d_in[4];
    const float* Wo   = (const float*)d_in[5];
    const float* bo   = (const float*)d_in[6];
    float* out = (float*)d_out;

    float *q, *attn;
    __half *kh, *vh;
    __nv_bfloat16 *whi, *wlo;
    cudaGetSymbolAddress((void**)&q,    g_q);
    cudaGetSymbolAddress((void**)&kh,   g_kh);
    cudaGetSymbolAddress((void**)&vh,   g_vh);
    cudaGetSymbolAddress((void**)&attn, g_attn);
    cudaGetSymbolAddress((void**)&whi,  g_whi);
    cudaGetSymbolAddress((void**)&wlo,  g_wlo);

    // Raise dynamic smem cap (idempotent; not a stream op; every call).
    cudaFuncSetAttribute(gemm_bf16,
                         cudaFuncAttributeMaxDynamicSharedMemorySize,
                         GSMEM_BYTES);

    convert_w<<<(4 * WELEM + 255) / 256, 256>>>(Wq, Wk, Wv, Wo);

    const int mb = (MROWS + 63) / 64;   // 313
    gemm_bf16<<<dim3(mb, 3), 256, GSMEM_BYTES>>>(x, whi, wlo, nullptr, q, kh, vh);

    attn_kernel<<<MROWS, 128>>>(kidx);

    gemm_bf16<<<dim3(mb, 1), 256, GSMEM_BYTES>>>(attn, whi + 3 * WELEM,
                                                 wlo + 3 * WELEM, bo,
                                                 out, nullptr, nullptr);
}

// round 8
// speedup vs baseline: 2.8322x; 1.1472x over previous
#include <cuda_runtime.h>
#include <cuda_bf16.h>
#include <cuda_fp16.h>
#include <math.h>

// Problem constants: B=4, L=5000, D=128, H=8, d=16, K=32
#define LQ    5000
#define MROWS 20000          // B*L  (divisible by 32)
#define DDIM  128
#define KSEL  32
#define WELEM (DDIM*DDIM)    // 16384
#define NTILES (MROWS/32)    // 625

// Scratch (allocation-free rule: __device__ globals)
__device__ float  g_q[MROWS * DDIM];
__device__ __half g_kh[MROWS * DDIM];
__device__ __half g_vh[MROWS * DDIM];
__device__ float  g_attn[MROWS * DDIM];
__device__ __nv_bfloat16 g_whi[4 * WELEM];
__device__ __nv_bfloat16 g_wlo[4 * WELEM];

// ---------------------------------------------------------------------------
__device__ __forceinline__ void bf16_split(float v, __nv_bfloat16& hi, __nv_bfloat16& lo)
{
    hi = __float2bfloat16(v);
    lo = __float2bfloat16(v - __bfloat162float(hi));
}

// W conversion: 4 x 16384 elements (tiny)
__global__ __launch_bounds__(256) void convert_w(const float* __restrict__ wq,
                                                 const float* __restrict__ wk,
                                                 const float* __restrict__ wv,
                                                 const float* __restrict__ wo)
{
    int i = blockIdx.x * blockDim.x + threadIdx.x;
    if (i >= 4 * WELEM) return;
    const float* src[4] = { wq, wk, wv, wo };
    float v = src[i >> 14][i & (WELEM - 1)];
    __nv_bfloat16 hi, lo;
    bf16_split(v, hi, lo);
    g_whi[i] = hi;
    g_wlo[i] = lo;
}

// ---------------------------------------------------------------------------
// Persistent-W 3xBF16 tensor GEMM: C[m][n] = sum_k A[m][k]*W[n][k] (+bias).
// W (hi+lo) resident in smem for the whole block; block grid-strides over
// 32-row A tiles (625 total), A double-buffered with register staging.
// 256 thr / 8 warps, warp grid 2m x 4n -> warp tile m16 x n32.
// Row stride 136 elem (272 B): ldmatrix 8-row phases hit 8 distinct 16B
// slots mod 128 B -> conflict-free. One k-sweep (8 steps), 1 sync/tile.
// ---------------------------------------------------------------------------
#define MMA_BF16(d, a, b)                                                   \
    asm volatile(                                                           \
        "mma.sync.aligned.m16n8k16.row.col.f32.bf16.bf16.f32 "              \
        "{%0,%1,%2,%3}, {%4,%5,%6,%7}, {%8,%9}, {%0,%1,%2,%3};"             \
        : "+f"(d[0]), "+f"(d[1]), "+f"(d[2]), "+f"(d[3])                    \
        : "r"(a[0]), "r"(a[1]), "r"(a[2]), "r"(a[3]), "r"(b[0]), "r"(b[1]))

__device__ __forceinline__ void ldsm4(unsigned* r, unsigned addr)
{
    asm volatile("ldmatrix.sync.aligned.m8n8.x4.shared.b16 {%0,%1,%2,%3}, [%4];"
                 : "=r"(r[0]), "=r"(r[1]), "=r"(r[2]), "=r"(r[3]) : "r"(addr));
}

#define SROWW   136                        // row stride in bf16 elems (272 B)
#define WPLANE  (128 * SROWW)              // 17408 elems
#define ATILE   (32 * SROWW)               // 4352 elems per A plane
#define OFF_WL  WPLANE                     // elem offsets
#define OFF_A   (2 * WPLANE)               // A buffers start (hi,lo per buf)
#define ABUF    (2 * ATILE)                // one A buffer (hi+lo)
#define GSMEM_ELEM (2 * WPLANE + 2 * ABUF) // 52224 elems
#define GSMEM_BYTES (GSMEM_ELEM * 2)       // 104448 B

__global__ __launch_bounds__(256, 2) void gemm_bf16(const float* __restrict__ A,
                                                    const __nv_bfloat16* __restrict__ WhiB,
                                                    const __nv_bfloat16* __restrict__ WloB,
                                                    const float* __restrict__ bias,
                                                    float* __restrict__ Cf,
                                                    __half* __restrict__ Ck,
                                                    __half* __restrict__ Cv,
                                                    int wsel)
{
    extern __shared__ __nv_bfloat16 smem[];

    const int y    = blockIdx.y;
    const int widx = wsel + y;
    const __nv_bfloat16* Wh = WhiB + widx * WELEM;
    const __nv_bfloat16* Wl = WloB + widx * WELEM;

    const int tid  = threadIdx.x;
    const int w    = tid >> 5;
    const int lane = tid & 31;
    const int wm   = (w >> 2) * 16;     // 2 warps in m
    const int wn   = (w & 3) * 32;      // 4 warps in n
    const int fr   = lane >> 2;
    const int fc   = (lane & 3) * 2;

    // ---- load W (hi+lo) into smem, once ----
    #pragma unroll
    for (int it = 0; it < 8; it++) {
        int i   = tid + it * 256;            // 0..2047 (uint4 granules)
        int row = i >> 4;
        int seg = i & 15;
        *(uint4*)&smem[row * SROWW + seg * 8] =
            *(const uint4*)&Wh[row * DDIM + seg * 8];
        *(uint4*)&smem[OFF_WL + row * SROWW + seg * 8] =
            *(const uint4*)&Wl[row * DDIM + seg * 8];
    }

    const unsigned sbase = (unsigned)__cvta_generic_to_shared(&smem[0]);
    const unsigned laneA = (unsigned)((wm + (lane & 15)) * (SROWW * 2)
                                      + ((lane >> 4) & 1) * 16);
    const unsigned laneB = (unsigned)((wn + ((lane >> 4) & 1) * 8 + (lane & 7)) * (SROWW * 2)
                                      + ((lane >> 3) & 1) * 16);
    const unsigned aoff[2] = { (unsigned)(OFF_A * 2), (unsigned)((OFF_A + ABUF) * 2) };

    // A staging: thread owns row ar (8 thr/row), 16 floats at seg as*16
    const int ar = tid >> 3;            // 0..31
    const int as = tid & 7;

    float4 aR[4];
    auto stage = [&](int mt) {
        const float4* s = (const float4*)&A[(size_t)(mt * 32 + ar) * DDIM + as * 16];
        aR[0] = s[0]; aR[1] = s[1]; aR[2] = s[2]; aR[3] = s[3];
    };
    auto commit = [&](int b) {
        __nv_bfloat16* ah = &smem[OFF_A + b * ABUF];
        __nv_bfloat16* al = ah + ATILE;
        union { __nv_bfloat16 h[16]; uint4 u[2]; } H, L;
        const float* af = (const float*)aR;
        #pragma unroll
        for (int i = 0; i < 16; i++) bf16_split(af[i], H.h[i], L.h[i]);
        uint4* dh = (uint4*)&ah[ar * SROWW + as * 16];
        uint4* dl = (uint4*)&al[ar * SROWW + as * 16];
        dh[0] = H.u[0]; dh[1] = H.u[1];
        dl[0] = L.u[0]; dl[1] = L.u[1];
    };

    int mt = blockIdx.x;
    int buf = 0;
    if (mt < NTILES) { stage(mt); commit(0); }
    __syncthreads();                     // covers W load + first A commit

    while (mt < NTILES) {
        const int nxt = mt + gridDim.x;
        if (nxt < NTILES) stage(nxt);

        float acc[4][4] = {};
        const unsigned ab = sbase + aoff[buf];

        #pragma unroll
        for (int ks = 0; ks < 8; ks++) {
            unsigned ah[4], al[4];
            ldsm4(ah, ab + laneA + (unsigned)(ks * 32));
            ldsm4(al, ab + (unsigned)(ATILE * 2) + laneA + (unsigned)(ks * 32));
            #pragma unroll
            for (int ntp = 0; ntp < 2; ntp++) {
                unsigned bh[4], bl[4];
                const unsigned bo = laneB + (unsigned)(ntp * 16 * SROWW * 2 + ks * 32);
                ldsm4(bh, sbase + bo);
                ldsm4(bl, sbase + (unsigned)(OFF_WL * 2) + bo);
                MMA_BF16(acc[ntp * 2],     ah, (bh + 0));
                MMA_BF16(acc[ntp * 2],     ah, (bl + 0));
                MMA_BF16(acc[ntp * 2],     al, (bh + 0));
                MMA_BF16(acc[ntp * 2 + 1], ah, (bh + 2));
                MMA_BF16(acc[ntp * 2 + 1], ah, (bl + 2));
                MMA_BF16(acc[ntp * 2 + 1], al, (bh + 2));
            }
        }

        // epilogue for tile mt
        const int mrow = mt * 32 + wm + fr;
        if (y == 0) {
            #pragma unroll
            for (int nt = 0; nt < 4; nt++) {
                const int n = wn + nt * 8 + fc;
                float2 bb = make_float2(0.f, 0.f);
                if (bias) bb = *(const float2*)&bias[n];
                *(float2*)&Cf[(size_t)mrow * DDIM + n] =
                    make_float2(acc[nt][0] + bb.x, acc[nt][1] + bb.y);
                *(float2*)&Cf[(size_t)(mrow + 8) * DDIM + n] =
                    make_float2(acc[nt][2] + bb.x, acc[nt][3] + bb.y);
            }
        } else {
            __half* H = (y == 1) ? Ck : Cv;
            #pragma unroll
            for (int nt = 0; nt < 4; nt++) {
                const int n = wn + nt * 8 + fc;
                *(__half2*)&H[(size_t)mrow * DDIM + n] =
                    __floats2half2_rn(acc[nt][0], acc[nt][1]);
                *(__half2*)&H[(size_t)(mrow + 8) * DDIM + n] =
                    __floats2half2_rn(acc[nt][2], acc[nt][3]);
            }
        }

        if (nxt < NTILES) commit(buf ^ 1);
        __syncthreads();
        buf ^= 1;
        mt = nxt;
    }
}

// ---------------------------------------------------------------------------
// Attention: register-resident gather, fp16 K/V, fp32 Q/math.
// ---------------------------------------------------------------------------
__global__ __launch_bounds__(128) void attn_kernel(const int* __restrict__ kidx)
{
    __shared__ int   sIdx[KSEL];
    __shared__ float sS[8][33];
    __shared__ float sAcc[4][DDIM];

    const int bl   = blockIdx.x;
    const int l    = bl % LQ;
    const int base = bl - l;
    const int t    = threadIdx.x;
    const int w    = t >> 5;
    const int lane = t & 31;
    const int h    = lane >> 2;

    if (t < KSEL) sIdx[t] = kidx[l * KSEL + t];

    const float4 q4 = *(const float4*)&g_q[(size_t)bl * DDIM + lane * 4];
    __syncthreads();

    int rows[8];
    #pragma unroll
    for (int i = 0; i < 8; i++) rows[i] = base + sIdx[i * 4 + w];

    #pragma unroll
    for (int i = 0; i < 8; i++) {
        const uint2 kv = *(const uint2*)&g_kh[(size_t)rows[i] * DDIM + lane * 4];
        const float2 f0 = __half22float2(*(const __half2*)&kv.x);
        const float2 f1 = __half22float2(*(const __half2*)&kv.y);
        float p = f0.x * q4.x + f0.y * q4.y + f1.x * q4.z + f1.y * q4.w;
        p += __shfl_xor_sync(0xffffffffu, p, 1);
        p += __shfl_xor_sync(0xffffffffu, p, 2);
        if ((lane & 3) == 0) sS[h][i * 4 + w] = p * 0.25f;
    }
    __syncthreads();

    #pragma unroll
    for (int j = 0; j < 2; j++) {
        const int hh = w * 2 + j;
        const float v = sS[hh][lane];
        float mx = v;
        #pragma unroll
        for (int ofs = 16; ofs; ofs >>= 1)
            mx = fmaxf(mx, __shfl_xor_sync(0xffffffffu, mx, ofs));
        const float e = __expf(v - mx);
        float sum = e;
        #pragma unroll
        for (int ofs = 16; ofs; ofs >>= 1)
            sum += __shfl_xor_sync(0xffffffffu, sum, ofs);
        sS[hh][lane] = e * __frcp_rn(sum);
    }
    __syncthreads();

    float4 acc = make_float4(0.f, 0.f, 0.f, 0.f);
    #pragma unroll
    for (int i = 0; i < 8; i++) {
        const uint2 vv = *(const uint2*)&g_vh[(size_t)rows[i] * DDIM + lane * 4];
        const float2 f0 = __half22float2(*(const __half2*)&vv.x);
        const float2 f1 = __half22float2(*(const __half2*)&vv.y);
        const float a = sS[h][i * 4 + w];
        acc.x += a * f0.x;
        acc.y += a * f0.y;
        acc.z += a * f1.x;
        acc.w += a * f1.y;
    }
    *(float4*)&sAcc[w][lane * 4] = acc;
    __syncthreads();

    g_attn[(size_t)bl * DDIM + t] = sAcc[0][t] + sAcc[1][t] + sAcc[2][t] + sAcc[3][t];
}

// ---------------------------------------------------------------------------
extern "C" void kernel_launch(void* const* d_in, const int* in_sizes, int n_in,
                              void* d_out, int out_size)
{
    const float* x    = (const float*)d_in[0];
    const int*   kidx = (const int*)d_in[1];
    const float* Wq   = (const float*)d_in[2];
    const float* Wk   = (const float*)d_in[3];
    const float* Wv   = (const float*)d_in[4];
    const float* Wo   = (const float*)d_in[5];
    const float* bo   = (const float*)d_in[6];
    float* out = (float*)d_out;

    float *q, *attn;
    __half *kh, *vh;
    __nv_bfloat16 *whi, *wlo;
    cudaGetSymbolAddress((void**)&q,    g_q);
    cudaGetSymbolAddress((void**)&kh,   g_kh);
    cudaGetSymbolAddress((void**)&vh,   g_vh);
    cudaGetSymbolAddress((void**)&attn, g_attn);
    cudaGetSymbolAddress((void**)&whi,  g_whi);
    cudaGetSymbolAddress((void**)&wlo,  g_wlo);

    // Raise dynamic smem cap (idempotent; not a stream op; every call).
    cudaFuncSetAttribute(gemm_bf16,
                         cudaFuncAttributeMaxDynamicSharedMemorySize,
                         GSMEM_BYTES);

    convert_w<<<(4 * WELEM + 255) / 256, 256>>>(Wq, Wk, Wv, Wo);

    // QKV: 96 x 3 = 288 persistent blocks (~2/SM), each ~6-7 m-tiles.
    gemm_bf16<<<dim3(96, 3), 256, GSMEM_BYTES>>>(x, whi, wlo, nullptr,
                                                 q, kh, vh, 0);

    attn_kernel<<<MROWS, 128>>>(kidx);

    // Wo: 288 x 1 persistent blocks, weight index 3, bias, fp32 out.
    gemm_bf16<<<dim3(288, 1), 256, GSMEM_BYTES>>>(attn, whi, wlo, bo,
                                                  out, nullptr, nullptr, 3);
}